// round 4
// baseline (speedup 1.0000x reference)
#include <cuda_runtime.h>
#include <math.h>

// Problem shape (fixed by the dataset): B=4096 rows, N=32768 cols.
#define NCE_B 4096

// Scratch (no cudaMalloc allowed). Zero-initialized at module load.
__device__ float g_row_loss[NCE_B];
__device__ unsigned int g_ticket = 0;   // last-block fusion counter; reset each call

__device__ __forceinline__ float tanh_approx(float x) {
    float y;
    asm("tanh.approx.f32 %0, %1;" : "=f"(y) : "f"(x));
    return y;
}

// e = exp(sigmoid(s)/T) = exp2(KH + KH*tanh(0.5*s)),  KH = 0.5*(1/T)*log2(e)
#define NCE_KH 10.30496457777831f

__device__ __forceinline__ void nce_accum(const float4 sv, const float4 lv,
                                          float& num, float& den)
{
    float t0 = tanh_approx(0.5f * sv.x);
    float t1 = tanh_approx(0.5f * sv.y);
    float t2 = tanh_approx(0.5f * sv.z);
    float t3 = tanh_approx(0.5f * sv.w);
    float e0 = exp2f(fmaf(NCE_KH, t0, NCE_KH));
    float e1 = exp2f(fmaf(NCE_KH, t1, NCE_KH));
    float e2 = exp2f(fmaf(NCE_KH, t2, NCE_KH));
    float e3 = exp2f(fmaf(NCE_KH, t3, NCE_KH));
    den += e0; num = fmaf(e0, lv.x, num);
    den += e1; num = fmaf(e1, lv.y, num);
    den += e2; num = fmaf(e2, lv.z, num);
    den += e3; num = fmaf(e3, lv.w, num);
}

// ---------------------------------------------------------------------------
// One CTA per row, 256 threads. Software-pipelined dual-stream float4 loads:
// each thread walks two halves of the row simultaneously and prefetches the
// next iteration's 4 loads before computing the current one -> 8 independent
// 16B loads continuously in flight per thread.
// Row loss -> g_row_loss; last CTA reduces the mean (deterministic order).
// ---------------------------------------------------------------------------
__global__ __launch_bounds__(256) void nce_fused_kernel(
    const float4* __restrict__ scores,
    const float4* __restrict__ labels,
    float* __restrict__ out,
    int n4)  // N/4 per row (8192)
{
    const int row = blockIdx.x;
    const float4* __restrict__ s = scores + (size_t)row * n4;
    const float4* __restrict__ l = labels + (size_t)row * n4;

    const int half = n4 >> 1;            // 4096
    const int iters = half / 256;        // 16

    float num = 0.0f, den = 0.0f;

    int i = threadIdx.x;
    // Prologue: first iteration's 4 loads
    float4 sa = __ldcs(s + i);
    float4 sb = __ldcs(s + i + half);
    float4 la = __ldcs(l + i);
    float4 lb = __ldcs(l + i + half);

    #pragma unroll 1
    for (int k = 0; k < iters - 1; ++k) {
        const int j = i + 256;
        // Prefetch next iteration (4 independent loads issued before any use)
        float4 nsa = __ldcs(s + j);
        float4 nsb = __ldcs(s + j + half);
        float4 nla = __ldcs(l + j);
        float4 nlb = __ldcs(l + j + half);

        // Compute current iteration (overlaps with outstanding prefetches)
        nce_accum(sa, la, num, den);
        nce_accum(sb, lb, num, den);

        sa = nsa; sb = nsb; la = nla; lb = nlb;
        i = j;
    }
    // Epilogue
    nce_accum(sa, la, num, den);
    nce_accum(sb, lb, num, den);

    // Warp reduction
    #pragma unroll
    for (int off = 16; off > 0; off >>= 1) {
        num += __shfl_xor_sync(0xffffffffu, num, off);
        den += __shfl_xor_sync(0xffffffffu, den, off);
    }

    __shared__ float s_num[8];
    __shared__ float s_den[8];
    __shared__ bool  s_last;
    const int lane = threadIdx.x & 31;
    const int wid  = threadIdx.x >> 5;
    if (lane == 0) { s_num[wid] = num; s_den[wid] = den; }
    __syncthreads();

    if (wid == 0) {
        float n2 = (lane < 8) ? s_num[lane] : 0.0f;
        float d2 = (lane < 8) ? s_den[lane] : 0.0f;
        #pragma unroll
        for (int off = 4; off > 0; off >>= 1) {
            n2 += __shfl_xor_sync(0xffffffffu, n2, off);
            d2 += __shfl_xor_sync(0xffffffffu, d2, off);
        }
        if (lane == 0) {
            float ratio = n2 / (d2 + 1e-12f) + 1e-12f;
            g_row_loss[row] = -logf(ratio);
            __threadfence();
            unsigned int t = atomicAdd(&g_ticket, 1u);
            s_last = (t == (unsigned int)(gridDim.x - 1));
        }
    }
    __syncthreads();

    // Last CTA: reduce the mean over all rows (fixed order -> deterministic),
    // write result, reset ticket for the next graph replay.
    if (s_last) {
        float acc = 0.0f;
        #pragma unroll
        for (int r = threadIdx.x; r < NCE_B; r += 256)
            acc += __ldcg(&g_row_loss[r]);   // L2 read: skip L1, see fenced data

        #pragma unroll
        for (int off = 16; off > 0; off >>= 1)
            acc += __shfl_xor_sync(0xffffffffu, acc, off);

        if (lane == 0) { s_num[wid] = acc; }
        __syncthreads();
        if (wid == 0) {
            float v = (lane < 8) ? s_num[lane] : 0.0f;
            #pragma unroll
            for (int off = 4; off > 0; off >>= 1)
                v += __shfl_xor_sync(0xffffffffu, v, off);
            if (lane == 0) {
                *out = v * (1.0f / (float)NCE_B);
                g_ticket = 0;              // restore state for next replay
                __threadfence();
            }
        }
    }
}

extern "C" void kernel_launch(void* const* d_in, const int* in_sizes, int n_in,
                              void* d_out, int out_size)
{
    const float4* scores = (const float4*)d_in[0];
    const float4* labels = (const float4*)d_in[1];
    float* out = (float*)d_out;

    const int total = in_sizes[0];       // B * N
    const int n = total / NCE_B;         // N = 32768
    const int n4 = n / 4;                // float4 count per row

    nce_fused_kernel<<<NCE_B, 256>>>(scores, labels, out, n4);
}